// round 3
// baseline (speedup 1.0000x reference)
#include <cuda_runtime.h>

// Problem constants (fixed by the dataset)
#define NN      262144            // nodes per tree (2^18)
#define NT      12                // B*C trees
#define HWPX    1048576           // H*W (2^20)
#define T0      2048              // exactly-solved prefix per tree (2^11)
#define TOTAL   (NT * NN)
#define NPIX    (NT * HWPX)

// Scratch (allocation-free rule: __device__ globals)
// g_node: packed {contrib0, contrib1, contrib2, parent-as-float-bits}
__device__ float4 g_node[TOTAL];
// g_F: final per-node filtered values {f0,f1,f2,_}
__device__ float4 g_F[TOTAL];

__device__ __forceinline__ float sigmoidf_(float x) {
    return 1.0f / (1.0f + expf(-x));
}

// ---------------------------------------------------------------------------
// Kernel A: per-node scores -> contrib, packed with parent pointer.
// 4 nodes per thread; stream inputs (ldcs) so g_node stays L2-resident.
// ---------------------------------------------------------------------------
__global__ void k_contrib(const float4* __restrict__ attrs4,   // 3 float4 per 4 nodes
                          const float4* __restrict__ residue4,
                          const float* __restrict__ W0,
                          const float* __restrict__ W1,
                          const float* __restrict__ W2,
                          const float* __restrict__ b0,
                          const float* __restrict__ b1,
                          const float* __restrict__ b2,
                          const int4*  __restrict__ parent4) {
    int t = blockIdx.x * blockDim.x + threadIdx.x;
    if (t >= TOTAL / 4) return;

    float4 A0 = __ldcs(&attrs4[3 * t + 0]);   // a0[0] a1[0] a2[0] a0[1]
    float4 A1 = __ldcs(&attrs4[3 * t + 1]);   // a1[1] a2[1] a0[2] a1[2]
    float4 A2 = __ldcs(&attrs4[3 * t + 2]);   // a2[2] a0[3] a1[3] a2[3]
    float4 R  = __ldcs(&residue4[t]);
    int4   P  = __ldcs(&parent4[t]);

    const float w0  = __ldg(W0);
    const float w10 = __ldg(&W1[0]);
    const float w11 = __ldg(&W1[1]);
    const float w2  = __ldg(W2);
    const float B0 = __ldg(b0), B1 = __ldg(b1), B2 = __ldg(b2);

    float a0[4] = {A0.x, A0.w, A1.z, A2.y};
    float a1[4] = {A0.y, A1.x, A1.w, A2.z};
    float a2[4] = {A0.z, A1.y, A2.x, A2.w};
    float r[4]  = {R.x, R.y, R.z, R.w};
    int   p[4]  = {P.x, P.y, P.z, P.w};

    float4* outp = g_node + 4 * (size_t)t;
#pragma unroll
    for (int k = 0; k < 4; k++) {
        float c0 = sigmoidf_(fmaf(a0[k], w0, B0)) * r[k];
        float c1 = sigmoidf_(fmaf(a2[k], w11, fmaf(a1[k], w10, B1))) * r[k];
        float c2 = sigmoidf_(fmaf(a1[k], w2, B2)) * r[k];
        outp[k] = make_float4(c0, c1, c2, __int_as_float(p[k]));
    }
}

// ---------------------------------------------------------------------------
// Kernel B: exact prefix solve for nodes [0,T0) per tree, written to g_F.
// In-smem Wyllie pointer jumping: 11 rounds cover any chain <= 2048.
// ---------------------------------------------------------------------------
__global__ void __launch_bounds__(1024, 1) k_prefix() {
    __shared__ float4 sm[T0];
    const int tree = blockIdx.x;
    const float4* nb = g_node + (size_t)tree * NN;

    for (int i = threadIdx.x; i < T0; i += blockDim.x)
        sm[i] = nb[i];
    __syncthreads();

    const int e0 = threadIdx.x;
    const int e1 = threadIdx.x + 1024;

    for (int r = 0; r < 11; r++) {
        float4 v0 = sm[e0];
        float4 v1 = sm[e1];
        int p0 = __float_as_int(v0.w);
        int p1 = __float_as_int(v1.w);
        if (p0 < T0) {
            float4 o = sm[p0];
            v0.x += o.x; v0.y += o.y; v0.z += o.z; v0.w = o.w;
        }
        if (p1 < T0) {
            float4 o = sm[p1];
            v1.x += o.x; v1.y += o.y; v1.z += o.z; v1.w = o.w;
        }
        __syncthreads();
        sm[e0] = v0;
        sm[e1] = v1;
        __syncthreads();
    }

    float4* Fb = g_F + (size_t)tree * NN;
    for (int i = threadIdx.x; i < T0; i += blockDim.x) {
        float4 v = sm[i];
        Fb[i] = make_float4(v.x, v.y, v.z, 0.0f);
    }
}

// ---------------------------------------------------------------------------
// Kernel C (cascade, ILP=4): finalize F for nodes [start, end) of every tree.
// Each thread owns 4 independent chains (strided by `span` for coalescing),
// advanced in lockstep so each loop iteration has up to 4 loads in flight.
// grid: (ceil(span/256), NT), span = ceil((end-start)/4)
// ---------------------------------------------------------------------------
__global__ void k_cascade(int start, int end, int span) {
    const int tree = blockIdx.y;
    const int tid  = blockIdx.x * blockDim.x + threadIdx.x;

    const float4* nb = g_node + (size_t)tree * NN;
    float4*       Fb = g_F    + (size_t)tree * NN;

    int   node[4], p[4];
    float ax[4], ay[4], az[4];

#pragma unroll
    for (int k = 0; k < 4; k++) {
        int n = start + tid + k * span;
        node[k] = n;
        if (n < end) {
            float4 v = __ldg(&nb[n]);
            ax[k] = v.x; ay[k] = v.y; az[k] = v.z;
            p[k] = __float_as_int(v.w);
        } else {
            ax[k] = ay[k] = az[k] = 0.0f;
            p[k] = -1;   // inactive (< start)
        }
    }

    bool any = true;
    while (any) {
        any = false;
        float4 u[4];
        bool act[4];
#pragma unroll
        for (int k = 0; k < 4; k++) {
            act[k] = (p[k] >= start);
            if (act[k]) u[k] = __ldg(&nb[p[k]]);
        }
#pragma unroll
        for (int k = 0; k < 4; k++) {
            if (act[k]) {
                ax[k] += u[k].x; ay[k] += u[k].y; az[k] += u[k].z;
                p[k] = __float_as_int(u[k].w);
                any = any || (p[k] >= start);
            }
        }
    }

    float4 f[4];
#pragma unroll
    for (int k = 0; k < 4; k++)
        if (node[k] < end) f[k] = __ldg(&Fb[p[k]]);
#pragma unroll
    for (int k = 0; k < 4; k++)
        if (node[k] < end)
            Fb[node[k]] = make_float4(ax[k] + f[k].x, ay[k] + f[k].y,
                                      az[k] + f[k].z, 0.0f);
}

// ---------------------------------------------------------------------------
// Kernel D: pixel gather, 8 pixels per thread. One 16B gather serves all
// 3 output channels; coalesced float4 stores per channel plane.
// ---------------------------------------------------------------------------
__global__ void k_gather(const int4* __restrict__ pix4,
                         float* __restrict__ out) {
    int t = blockIdx.x * blockDim.x + threadIdx.x;
    if (t >= NPIX / 8) return;

    const int q0   = 8 * t;              // first pixel (global)
    const int tree = q0 >> 20;           // HWPX = 2^20
    const int p    = q0 & (HWPX - 1);

    int4 ndA = __ldcs(&pix4[2 * t]);
    int4 ndB = __ldcs(&pix4[2 * t + 1]);

    const float4* Fb = g_F + (size_t)tree * NN;
    float4 F0 = __ldg(&Fb[ndA.x]);
    float4 F1 = __ldg(&Fb[ndA.y]);
    float4 F2 = __ldg(&Fb[ndA.z]);
    float4 F3 = __ldg(&Fb[ndA.w]);
    float4 F4 = __ldg(&Fb[ndB.x]);
    float4 F5 = __ldg(&Fb[ndB.y]);
    float4 F6 = __ldg(&Fb[ndB.z]);
    float4 F7 = __ldg(&Fb[ndB.w]);

    float* o = out + (size_t)tree * 3 * HWPX + p;
    __stcs((float4*)(o),                make_float4(F0.x, F1.x, F2.x, F3.x));
    __stcs((float4*)(o + 4),            make_float4(F4.x, F5.x, F6.x, F7.x));
    __stcs((float4*)(o + HWPX),         make_float4(F0.y, F1.y, F2.y, F3.y));
    __stcs((float4*)(o + HWPX + 4),     make_float4(F4.y, F5.y, F6.y, F7.y));
    __stcs((float4*)(o + 2 * HWPX),     make_float4(F0.z, F1.z, F2.z, F3.z));
    __stcs((float4*)(o + 2 * HWPX + 4), make_float4(F4.z, F5.z, F6.z, F7.z));
}

// ---------------------------------------------------------------------------
// Entry point
// Inputs: attrs, residue, W0, W1, W2, b0, b1, b2, parent, pixel_node
// ---------------------------------------------------------------------------
extern "C" void kernel_launch(void* const* d_in, const int* in_sizes, int n_in,
                              void* d_out, int out_size) {
    const float* attrs   = (const float*)d_in[0];
    const float* residue = (const float*)d_in[1];
    const float* W0      = (const float*)d_in[2];
    const float* W1      = (const float*)d_in[3];
    const float* W2      = (const float*)d_in[4];
    const float* b0      = (const float*)d_in[5];
    const float* b1      = (const float*)d_in[6];
    const float* b2      = (const float*)d_in[7];
    const int*   parent  = (const int*)d_in[8];
    const int*   pix     = (const int*)d_in[9];
    float*       out     = (float*)d_out;

    {
        int threads = 256;
        int blocks = (TOTAL / 4 + threads - 1) / threads;
        k_contrib<<<blocks, threads>>>((const float4*)attrs, (const float4*)residue,
                                       W0, W1, W2, b0, b1, b2, (const int4*)parent);
    }
    k_prefix<<<NT, 1024>>>();

    // Cascaded finalization: each stage walks only within its own range.
    const int stages[5] = {2048, 8192, 32768, 131072, 262144};
    for (int s = 0; s < 4; s++) {
        int start = stages[s], end = stages[s + 1];
        int span = (end - start + 3) / 4;      // nodes per ILP lane
        int threads = 256;
        dim3 grid((span + threads - 1) / threads, NT);
        k_cascade<<<grid, threads>>>(start, end, span);
    }

    {
        int threads = 256;
        int blocks = (NPIX / 8 + threads - 1) / threads;
        k_gather<<<blocks, threads>>>((const int4*)pix, out);
    }
}